// round 1
// baseline (speedup 1.0000x reference)
#include <cuda_runtime.h>

// Problem constants
#define SS   96
#define BB   16
#define DD   512
#define HIDN 128
#define NR   (SS * BB)   // 1536 rows

// Scratch for intermediate activations (allocation-free rule: __device__ globals)
__device__ float g_ha[NR * HIDN];   // ha + b1 pre-added
__device__ float g_hb[NR * HIDN];

// ---------------------------------------------------------------------------
// Stage 1: C[r][h] = sum_k X[r][k] * W[h][k]   (X: 1536x512, W: 128x512 slice)
// z=0: X=embeds,     W=W1[:, 0:512],   C=g_ha (+b1)
// z=1: X=embeds_cmp, W=W1[:, 512:1024],C=g_hb
// Tiles: BM=64, BN=64, BK=32, 256 threads, 4x4 micro-tile per thread.
// ---------------------------------------------------------------------------
#define BM 64
#define BN 64
#define BK 32
#define PADM 68   // 64+4: breaks store conflicts, keeps 16B alignment
#define PADN 68

__global__ __launch_bounds__(256) void stage1_kernel(
    const float* __restrict__ X0, const float* __restrict__ X1,
    const float* __restrict__ W1, const float* __restrict__ b1)
{
    __shared__ float sX[BK][PADM];
    __shared__ float sW[BK][PADN];

    const int mt = blockIdx.x;   // 0..23
    const int nt = blockIdx.y;   // 0..1
    const int z  = blockIdx.z;   // 0 or 1

    const float* __restrict__ X = z ? X1 : X0;
    const float* __restrict__ W = W1 + (z ? DD : 0);  // row stride 2*DD
    float* __restrict__ C = z ? g_hb : g_ha;

    const int tid = threadIdx.x;
    const int rg  = tid >> 4;    // 0..15 -> rows rg*4 .. rg*4+3
    const int cg  = tid & 15;    // 0..15 -> cols cg*4 .. cg*4+3
    const int m0  = mt * BM;
    const int n0  = nt * BN;

    float acc[4][4];
    #pragma unroll
    for (int r = 0; r < 4; r++)
        #pragma unroll
        for (int c = 0; c < 4; c++) acc[r][c] = 0.0f;

    for (int k0 = 0; k0 < DD; k0 += BK) {
        // Load X tile (64x32) and W tile (64x32), transposed into [k][m]/[k][n]
        #pragma unroll
        for (int i = 0; i < 2; i++) {
            const int q   = tid + i * 256;   // 0..511
            const int row = q >> 3;          // 0..63
            const int kq  = q & 7;           // 0..7 (float4 index along k)

            float4 vx = *reinterpret_cast<const float4*>(
                &X[(size_t)(m0 + row) * DD + k0 + kq * 4]);
            sX[kq * 4 + 0][row] = vx.x;
            sX[kq * 4 + 1][row] = vx.y;
            sX[kq * 4 + 2][row] = vx.z;
            sX[kq * 4 + 3][row] = vx.w;

            float4 vw = *reinterpret_cast<const float4*>(
                &W[(size_t)(n0 + row) * (2 * DD) + k0 + kq * 4]);
            sW[kq * 4 + 0][row] = vw.x;
            sW[kq * 4 + 1][row] = vw.y;
            sW[kq * 4 + 2][row] = vw.z;
            sW[kq * 4 + 3][row] = vw.w;
        }
        __syncthreads();

        #pragma unroll
        for (int k = 0; k < BK; k++) {
            float4 a = *reinterpret_cast<const float4*>(&sX[k][rg * 4]);
            float4 w = *reinterpret_cast<const float4*>(&sW[k][cg * 4]);
            float av[4] = {a.x, a.y, a.z, a.w};
            float wv[4] = {w.x, w.y, w.z, w.w};
            #pragma unroll
            for (int r = 0; r < 4; r++)
                #pragma unroll
                for (int c = 0; c < 4; c++)
                    acc[r][c] = fmaf(av[r], wv[c], acc[r][c]);
        }
        __syncthreads();
    }

    // Epilogue: add b1 into ha only (so stage2 computes relu(ha'+hb))
    float bias[4] = {0.0f, 0.0f, 0.0f, 0.0f};
    if (z == 0) {
        #pragma unroll
        for (int c = 0; c < 4; c++) bias[c] = b1[n0 + cg * 4 + c];
    }
    #pragma unroll
    for (int r = 0; r < 4; r++) {
        float4 o;
        o.x = acc[r][0] + bias[0];
        o.y = acc[r][1] + bias[1];
        o.z = acc[r][2] + bias[2];
        o.w = acc[r][3] + bias[3];
        *reinterpret_cast<float4*>(
            &C[(size_t)(m0 + rg * 4 + r) * HIDN + n0 + cg * 4]) = o;
    }
}

// ---------------------------------------------------------------------------
// Stage 2: out[i,j,b,c] = sum_h relu(ha'[i,b,h] + hb[j,b,h]) * W2[c,h] + b2[c]
// Grid (3,3,16): 32x32 (i,j) tile per block at fixed b. 256 threads,
// each thread computes 2x2 pairs (rows rg/rg+16 x cols cg/cg+16).
// ---------------------------------------------------------------------------
#define TI 32
#define TJ 32
#define PADH 132  // 128+4 -> 2-way instead of 16-way bank conflicts

__global__ __launch_bounds__(256) void stage2_kernel(
    const float* __restrict__ W2, const float* __restrict__ b2,
    float* __restrict__ out)
{
    __shared__ float sA[TI][PADH];
    __shared__ float sB[TJ][PADH];
    __shared__ float sW2[2 * HIDN];

    const int i0  = blockIdx.x * TI;
    const int j0  = blockIdx.y * TJ;
    const int b   = blockIdx.z;
    const int tid = threadIdx.x;

    // Fill smem: 32 rows x 128 floats each for ha and hb (rows of fixed b)
    #pragma unroll
    for (int i = 0; i < 4; i++) {
        const int q   = tid + i * 256;  // 0..1023
        const int row = q >> 5;         // 0..31
        const int hq  = q & 31;         // float4 index along h

        float4 va = *reinterpret_cast<const float4*>(
            &g_ha[((size_t)(i0 + row) * BB + b) * HIDN + hq * 4]);
        *reinterpret_cast<float4*>(&sA[row][hq * 4]) = va;

        float4 vb = *reinterpret_cast<const float4*>(
            &g_hb[((size_t)(j0 + row) * BB + b) * HIDN + hq * 4]);
        *reinterpret_cast<float4*>(&sB[row][hq * 4]) = vb;
    }
    if (tid < 64) {
        float4 w = *reinterpret_cast<const float4*>(&W2[tid * 4]);
        *reinterpret_cast<float4*>(&sW2[tid * 4]) = w;
    }
    __syncthreads();

    const int rg = tid >> 4;   // 0..15
    const int cg = tid & 15;   // 0..15

    float acc[2][2][2];
    #pragma unroll
    for (int ii = 0; ii < 2; ii++)
        #pragma unroll
        for (int jj = 0; jj < 2; jj++) {
            acc[ii][jj][0] = 0.0f;
            acc[ii][jj][1] = 0.0f;
        }

    #pragma unroll
    for (int hq = 0; hq < HIDN / 4; hq++) {
        float4 a0 = *reinterpret_cast<const float4*>(&sA[rg][hq * 4]);
        float4 a1 = *reinterpret_cast<const float4*>(&sA[rg + 16][hq * 4]);
        float4 q0 = *reinterpret_cast<const float4*>(&sB[cg][hq * 4]);
        float4 q1 = *reinterpret_cast<const float4*>(&sB[cg + 16][hq * 4]);
        float4 w0 = *reinterpret_cast<const float4*>(&sW2[hq * 4]);
        float4 w1 = *reinterpret_cast<const float4*>(&sW2[HIDN + hq * 4]);

        float av[2][4] = {{a0.x, a0.y, a0.z, a0.w}, {a1.x, a1.y, a1.z, a1.w}};
        float qv[2][4] = {{q0.x, q0.y, q0.z, q0.w}, {q1.x, q1.y, q1.z, q1.w}};
        float w0v[4]   = {w0.x, w0.y, w0.z, w0.w};
        float w1v[4]   = {w1.x, w1.y, w1.z, w1.w};

        #pragma unroll
        for (int ii = 0; ii < 2; ii++)
            #pragma unroll
            for (int jj = 0; jj < 2; jj++)
                #pragma unroll
                for (int l = 0; l < 4; l++) {
                    float v = fmaxf(av[ii][l] + qv[jj][l], 0.0f);
                    acc[ii][jj][0] = fmaf(v, w0v[l], acc[ii][jj][0]);
                    acc[ii][jj][1] = fmaf(v, w1v[l], acc[ii][jj][1]);
                }
    }

    const float bb0 = b2[0];
    const float bb1 = b2[1];
    #pragma unroll
    for (int ii = 0; ii < 2; ii++)
        #pragma unroll
        for (int jj = 0; jj < 2; jj++) {
            const int i = i0 + rg + ii * 16;
            const int j = j0 + cg + jj * 16;
            const size_t idx = (((size_t)i * SS + j) * BB + b) * 2;
            float2 o;
            o.x = acc[ii][jj][0] + bb0;
            o.y = acc[ii][jj][1] + bb1;
            *reinterpret_cast<float2*>(&out[idx]) = o;
        }
}

// ---------------------------------------------------------------------------
// Inputs (metadata order): embeds, umask, qmask, embeds_cmp, W1, b1, W2, b2
// umask/qmask are unused by the reference computation.
// ---------------------------------------------------------------------------
extern "C" void kernel_launch(void* const* d_in, const int* in_sizes, int n_in,
                              void* d_out, int out_size)
{
    const float* embeds     = (const float*)d_in[0];
    const float* embeds_cmp = (const float*)d_in[3];
    const float* W1         = (const float*)d_in[4];
    const float* b1         = (const float*)d_in[5];
    const float* W2         = (const float*)d_in[6];
    const float* b2         = (const float*)d_in[7];
    float* out = (float*)d_out;

    stage1_kernel<<<dim3(24, 2, 2), 256>>>(embeds, embeds_cmp, W1, b1);
    stage2_kernel<<<dim3(3, 3, 16), 256>>>(W2, b2, out);
}

// round 2
// speedup vs baseline: 1.0506x; 1.0506x over previous
#include <cuda_runtime.h>

// Problem constants
#define SS   96
#define BB   16
#define DD   512
#define HIDN 128
#define NR   (SS * BB)   // 1536 rows

// Scratch for intermediate activations (allocation-free rule: __device__ globals)
__device__ float g_ha[NR * HIDN];   // ha + b1 pre-added
__device__ float g_hb[NR * HIDN];

// ---------------------------------------------------------------------------
// Packed f32x2 helpers (sm_100+): one instruction, two independent FMAs.
// 64-bit reg lanes: {lo, hi} = (first float, second float) of a float2.
// ---------------------------------------------------------------------------
__device__ __forceinline__ unsigned long long ffma2(
    unsigned long long a, unsigned long long b, unsigned long long c)
{
    unsigned long long d;
    asm("fma.rn.f32x2 %0, %1, %2, %3;" : "=l"(d) : "l"(a), "l"(b), "l"(c));
    return d;
}

__device__ __forceinline__ unsigned long long dup2(float v)
{
    unsigned long long d;
    asm("mov.b64 %0, {%1, %1};" : "=l"(d) : "f"(v));
    return d;
}

__device__ __forceinline__ float2 unpk2(unsigned long long v)
{
    float2 f;
    asm("mov.b64 {%0, %1}, %2;" : "=f"(f.x), "=f"(f.y) : "l"(v));
    return f;
}

// ---------------------------------------------------------------------------
// Stage 1: C[r][h] = sum_k X[r][k] * W[h][k]   (X: 1536x512, W: 128x512 slice)
// z=0: X=embeds,     W=W1[:, 0:512],    C=g_ha (+b1)
// z=1: X=embeds_cmp, W=W1[:, 512:1024], C=g_hb
// BM=48, BN=64, BK=64, 256 threads, 3x4 micro-tile (rows rg,rg+16,rg+32 x
// cols cg*4..+3). Accumulators are f32x2 column-pairs.
// Grid: (32, 2, 2) = 128 blocks -> one wave on 148 SMs.
// ---------------------------------------------------------------------------
#define BM 48
#define BN 64
#define BK 64
#define PADX 49   // float2 units (8B); 48+1
#define PADW 68   // floats; 64+4 keeps 16B alignment for float4 reads

__global__ __launch_bounds__(256) void stage1_kernel(
    const float* __restrict__ X0, const float* __restrict__ X1,
    const float* __restrict__ W1, const float* __restrict__ b1)
{
    // X stored DUPLICATED: sX[k][m] = (x, x) so LDS.64 yields a ready f32x2 operand.
    __shared__ float2 sX[BK][PADX];
    // W stored TRANSPOSED k-major: sW[k][n]; float2 pairs along n are the
    // packed (c, c+1) operand read directly as 64-bit words.
    __shared__ float  sW[BK][PADW];

    const int mt = blockIdx.x;   // 0..31
    const int nt = blockIdx.y;   // 0..1
    const int z  = blockIdx.z;   // 0 or 1

    const float* __restrict__ X = z ? X1 : X0;
    const float* __restrict__ W = W1 + (z ? DD : 0);  // row stride 2*DD
    float* __restrict__ C = z ? g_hb : g_ha;

    const int tid = threadIdx.x;
    const int rg  = tid >> 4;    // 0..15
    const int cg  = tid & 15;    // 0..15
    const int m0  = mt * BM;
    const int n0  = nt * BN;

    unsigned long long acc[3][2];
    #pragma unroll
    for (int r = 0; r < 3; r++) { acc[r][0] = 0ull; acc[r][1] = 0ull; }

    for (int k0 = 0; k0 < DD; k0 += BK) {
        // --- Load X tile (48 rows x 64 k), duplicated-store transposed ---
        #pragma unroll
        for (int i = 0; i < 3; i++) {
            const int flat = tid + i * 256;   // 0..767
            const int row  = flat >> 4;       // 0..47
            const int kq   = flat & 15;       // 0..15
            float4 v = *reinterpret_cast<const float4*>(
                &X[(size_t)(m0 + row) * DD + k0 + kq * 4]);
            sX[kq * 4 + 0][row] = make_float2(v.x, v.x);
            sX[kq * 4 + 1][row] = make_float2(v.y, v.y);
            sX[kq * 4 + 2][row] = make_float2(v.z, v.z);
            sX[kq * 4 + 3][row] = make_float2(v.w, v.w);
        }
        // --- Load W tile (64 rows x 64 k), transposed store ---
        // Warp covers 8 rows x 4 k-quads: 16-sector coalesced loads,
        // 2-way STS conflicts only.
        #pragma unroll
        for (int i = 0; i < 4; i++) {
            const int flat = tid + i * 256;        // 0..1023
            const int lane = flat & 31;
            const int wi   = flat >> 5;            // 0..31
            const int kq   = (lane & 3) + ((wi >> 3) << 2);  // 0..15
            const int row  = (lane >> 2) + ((wi & 7) << 3);  // 0..63
            float4 v = *reinterpret_cast<const float4*>(
                &W[(size_t)(n0 + row) * (2 * DD) + k0 + kq * 4]);
            sW[kq * 4 + 0][row] = v.x;
            sW[kq * 4 + 1][row] = v.y;
            sW[kq * 4 + 2][row] = v.z;
            sW[kq * 4 + 3][row] = v.w;
        }
        __syncthreads();

        #pragma unroll
        for (int k = 0; k < BK; k++) {
            unsigned long long a0 = *reinterpret_cast<const unsigned long long*>(&sX[k][rg]);
            unsigned long long a1 = *reinterpret_cast<const unsigned long long*>(&sX[k][rg + 16]);
            unsigned long long a2 = *reinterpret_cast<const unsigned long long*>(&sX[k][rg + 32]);
            ulonglong2 w = *reinterpret_cast<const ulonglong2*>(&sW[k][cg * 4]);
            acc[0][0] = ffma2(a0, w.x, acc[0][0]);
            acc[0][1] = ffma2(a0, w.y, acc[0][1]);
            acc[1][0] = ffma2(a1, w.x, acc[1][0]);
            acc[1][1] = ffma2(a1, w.y, acc[1][1]);
            acc[2][0] = ffma2(a2, w.x, acc[2][0]);
            acc[2][1] = ffma2(a2, w.y, acc[2][1]);
        }
        __syncthreads();
    }

    // Epilogue: add b1 into ha only (stage2 computes relu(ha'+hb))
    float bias[4] = {0.0f, 0.0f, 0.0f, 0.0f};
    if (z == 0) {
        #pragma unroll
        for (int c = 0; c < 4; c++) bias[c] = b1[n0 + cg * 4 + c];
    }
    #pragma unroll
    for (int r = 0; r < 3; r++) {
        float2 p0 = unpk2(acc[r][0]);
        float2 p1 = unpk2(acc[r][1]);
        float4 o;
        o.x = p0.x + bias[0];
        o.y = p0.y + bias[1];
        o.z = p1.x + bias[2];
        o.w = p1.y + bias[3];
        *reinterpret_cast<float4*>(
            &C[(size_t)(m0 + rg + r * 16) * HIDN + n0 + cg * 4]) = o;
    }
}

// ---------------------------------------------------------------------------
// Stage 2: out[i,j,b,c] = sum_h relu(ha'[i,b,h] + hb[j,b,h]) * W2[c,h] + b2[c]
// Grid (3,3,16), 512 threads: 32x32 (i,j) tile at fixed b; each thread does
// 1x2 pairs (row rg, cols cg & cg+16). Output channels packed via f32x2 with
// W2 pre-packed as (c0,c1) pairs in smem.
// ---------------------------------------------------------------------------
#define TI 32
#define TJ 32
#define PADH 132  // 128+4 floats, 16B aligned

__global__ __launch_bounds__(512) void stage2_kernel(
    const float* __restrict__ W2, const float* __restrict__ b2,
    float* __restrict__ out)
{
    __shared__ float sA[TI][PADH];
    __shared__ float sB[TJ][PADH];
    __shared__ unsigned long long sW2p[HIDN];  // (W2[0][h], W2[1][h]) packed

    const int i0  = blockIdx.x * TI;
    const int j0  = blockIdx.y * TJ;
    const int b   = blockIdx.z;
    const int tid = threadIdx.x;

    // Fill smem: 32 rows x 128 floats for each of ha/hb (fixed b)
    #pragma unroll
    for (int i = 0; i < 2; i++) {
        const int q   = tid + i * 512;  // 0..1023
        const int row = q >> 5;         // 0..31
        const int hq  = q & 31;         // float4 index along h

        float4 va = *reinterpret_cast<const float4*>(
            &g_ha[((size_t)(i0 + row) * BB + b) * HIDN + hq * 4]);
        *reinterpret_cast<float4*>(&sA[row][hq * 4]) = va;

        float4 vb = *reinterpret_cast<const float4*>(
            &g_hb[((size_t)(j0 + row) * BB + b) * HIDN + hq * 4]);
        *reinterpret_cast<float4*>(&sB[row][hq * 4]) = vb;
    }
    if (tid < HIDN) {
        float w0 = W2[tid];           // W2[0][h]
        float w1 = W2[HIDN + tid];    // W2[1][h]
        unsigned long long p;
        asm("mov.b64 %0, {%1, %2};" : "=l"(p) : "f"(w0), "f"(w1));
        sW2p[tid] = p;
    }
    __syncthreads();

    const int rg = tid >> 4;   // 0..31
    const int cg = tid & 15;   // 0..15

    unsigned long long accA = 0ull;   // pair (i=rg, j=cg)
    unsigned long long accB = 0ull;   // pair (i=rg, j=cg+16)

    #pragma unroll
    for (int hq = 0; hq < HIDN / 4; hq++) {
        float4 a  = *reinterpret_cast<const float4*>(&sA[rg][hq * 4]);
        float4 q0 = *reinterpret_cast<const float4*>(&sB[cg][hq * 4]);
        float4 q1 = *reinterpret_cast<const float4*>(&sB[cg + 16][hq * 4]);
        ulonglong2 wA = *reinterpret_cast<const ulonglong2*>(&sW2p[hq * 4]);
        ulonglong2 wB = *reinterpret_cast<const ulonglong2*>(&sW2p[hq * 4 + 2]);

        float av[4] = {a.x, a.y, a.z, a.w};
        float q0v[4] = {q0.x, q0.y, q0.z, q0.w};
        float q1v[4] = {q1.x, q1.y, q1.z, q1.w};
        unsigned long long wv[4] = {wA.x, wA.y, wB.x, wB.y};

        #pragma unroll
        for (int l = 0; l < 4; l++) {
            float v0 = fmaxf(av[l] + q0v[l], 0.0f);
            accA = ffma2(dup2(v0), wv[l], accA);
            float v1 = fmaxf(av[l] + q1v[l], 0.0f);
            accB = ffma2(dup2(v1), wv[l], accB);
        }
    }

    const float bb0 = b2[0];
    const float bb1 = b2[1];

    {
        float2 r = unpk2(accA);
        const size_t idx = (((size_t)(i0 + rg) * SS + (j0 + cg)) * BB + b) * 2;
        float2 o; o.x = r.x + bb0; o.y = r.y + bb1;
        *reinterpret_cast<float2*>(&out[idx]) = o;
    }
    {
        float2 r = unpk2(accB);
        const size_t idx = (((size_t)(i0 + rg) * SS + (j0 + cg + 16)) * BB + b) * 2;
        float2 o; o.x = r.x + bb0; o.y = r.y + bb1;
        *reinterpret_cast<float2*>(&out[idx]) = o;
    }
}

// ---------------------------------------------------------------------------
// Inputs (metadata order): embeds, umask, qmask, embeds_cmp, W1, b1, W2, b2
// umask/qmask are unused by the reference computation.
// ---------------------------------------------------------------------------
extern "C" void kernel_launch(void* const* d_in, const int* in_sizes, int n_in,
                              void* d_out, int out_size)
{
    const float* embeds     = (const float*)d_in[0];
    const float* embeds_cmp = (const float*)d_in[3];
    const float* W1         = (const float*)d_in[4];
    const float* b1         = (const float*)d_in[5];
    const float* W2         = (const float*)d_in[6];
    const float* b2         = (const float*)d_in[7];
    float* out = (float*)d_out;

    stage1_kernel<<<dim3(32, 2, 2), 256>>>(embeds, embeds_cmp, W1, b1);
    stage2_kernel<<<dim3(3, 3, 16), 512>>>(W2, b2, out);
}

// round 4
// speedup vs baseline: 1.1784x; 1.1216x over previous
#include <cuda_runtime.h>

// Problem constants
#define SS   96
#define BB   16
#define DD   512
#define HIDN 128
#define NR   (SS * BB)   // 1536 rows

// Scratch (__device__ globals: allocation-free rule)
__device__ float g_Xt[2][DD * NR];     // transposed inputs: [k][r], 3MB each
__device__ float g_Wt[2][DD * HIDN];   // transposed W1 halves: [k][n]
__device__ float g_ha[NR * HIDN];      // ha + b1
__device__ float g_hb[NR * HIDN];

// ---------------------------------------------------------------------------
// f32x2 helpers
// ---------------------------------------------------------------------------
__device__ __forceinline__ unsigned long long ffma2(
    unsigned long long a, unsigned long long b, unsigned long long c)
{
    unsigned long long d;
    asm("fma.rn.f32x2 %0, %1, %2, %3;" : "=l"(d) : "l"(a), "l"(b), "l"(c));
    return d;
}
__device__ __forceinline__ unsigned long long dup2(float v)
{
    unsigned long long d;
    asm("mov.b64 %0, {%1, %1};" : "=l"(d) : "f"(v));
    return d;
}
__device__ __forceinline__ float2 unpk2(unsigned long long v)
{
    float2 f;
    asm("mov.b64 {%0, %1}, %2;" : "=f"(f.x), "=f"(f.y) : "l"(v));
    return f;
}

// cp.async 16B
__device__ __forceinline__ unsigned smem_u32(const void* p)
{
    unsigned a;
    asm("{ .reg .u64 t; cvta.to.shared.u64 t, %1; cvt.u32.u64 %0, t; }"
        : "=r"(a) : "l"(p));
    return a;
}
__device__ __forceinline__ void cp16(unsigned dst, const float* src)
{
    asm volatile("cp.async.cg.shared.global [%0], [%1], 16;" :: "r"(dst), "l"(src));
}
__device__ __forceinline__ void cp_commit() { asm volatile("cp.async.commit_group;"); }
__device__ __forceinline__ void cp_wait1()  { asm volatile("cp.async.wait_group 1;"); }
__device__ __forceinline__ void cp_wait0()  { asm volatile("cp.async.wait_group 0;"); }

// ---------------------------------------------------------------------------
// Kernel A: transpose X0/X1 -> g_Xt[z][k][r] and W1 halves -> g_Wt[z][k][n].
// Grid (49, 16, 2), 256 threads (tx 0..31, ty 0..7). 32x32 tiles, pad 33.
// ---------------------------------------------------------------------------
__global__ __launch_bounds__(256) void prep_kernel(
    const float* __restrict__ X0, const float* __restrict__ X1,
    const float* __restrict__ W1)
{
    __shared__ float t[32][33];
    const int tx = threadIdx.x & 31;
    const int ty = threadIdx.x >> 5;
    const int z  = blockIdx.z;

    if (blockIdx.x < 48) {
        const int r0 = blockIdx.x * 32;
        const int k0 = blockIdx.y * 32;
        const float* __restrict__ X = z ? X1 : X0;
        #pragma unroll
        for (int i = 0; i < 4; i++)
            t[ty + 8 * i][tx] = X[(size_t)(r0 + ty + 8 * i) * DD + k0 + tx];
        __syncthreads();
        #pragma unroll
        for (int i = 0; i < 4; i++)
            g_Xt[z][(size_t)(k0 + ty + 8 * i) * NR + r0 + tx] = t[tx][ty + 8 * i];
    } else {
        const int k0 = blockIdx.y * 32;
        for (int nt = 0; nt < 4; nt++) {
            const int n0 = nt * 32;
            __syncthreads();
            #pragma unroll
            for (int i = 0; i < 4; i++)
                t[ty + 8 * i][tx] =
                    W1[(size_t)(n0 + ty + 8 * i) * (2 * DD) + z * DD + k0 + tx];
            __syncthreads();
            #pragma unroll
            for (int i = 0; i < 4; i++)
                g_Wt[z][(size_t)(k0 + ty + 8 * i) * HIDN + n0 + tx] = t[tx][ty + 8 * i];
        }
    }
}

// ---------------------------------------------------------------------------
// Kernel B: stage1 GEMM on pre-transposed operands.
// C[r][h] = sum_k Xt[k][r] * Wt[k][h];  z=0 -> g_ha (+b1), z=1 -> g_hb.
// BM=BN=64, BK=32, 256 threads, 4 rows x 4 cols per thread, row-pair f32x2
// accumulators. Double-buffered cp.async fills. Grid (24, 2, 2) = 96 blocks.
// ---------------------------------------------------------------------------
#define S1BK  32
#define S1PAD 68   // floats per smem row (64 + 4), 16B-aligned

__global__ __launch_bounds__(256) void stage1_kernel(const float* __restrict__ b1)
{
    __shared__ float sX[2][S1BK][S1PAD];
    __shared__ float sW[2][S1BK][S1PAD];

    const int mt = blockIdx.x;   // 0..23
    const int nt = blockIdx.y;   // 0..1
    const int z  = blockIdx.z;

    const float* __restrict__ Xt = g_Xt[z];
    const float* __restrict__ Wt = g_Wt[z];
    float* __restrict__ C = z ? g_hb : g_ha;

    const int tid = threadIdx.x;
    const int rg  = tid >> 4;    // 0..15 -> rows rg*4..+3
    const int cg  = tid & 15;    // 0..15 -> cols cg*4..+3
    const int m0  = mt * 64;
    const int n0  = nt * 64;

    // cp.async chunk mapping: two 16B chunks per tile per thread
    const int ck0 = tid >> 4;          // k for chunk 0 (0..15)
    const int cq0 = tid & 15;          // m/n quad for chunk 0
    const int ck1 = (tid + 256) >> 4;  // 16..31
    const int cq1 = cq0;

    unsigned dstX0 = smem_u32(&sX[0][ck0][cq0 * 4]);
    unsigned dstX1 = smem_u32(&sX[0][ck1][cq1 * 4]);
    unsigned dstW0 = smem_u32(&sW[0][ck0][cq0 * 4]);
    unsigned dstW1 = smem_u32(&sW[0][ck1][cq1 * 4]);
    const unsigned bufStride = (unsigned)(S1BK * S1PAD * sizeof(float));

    const float* srcX0 = &Xt[(size_t)ck0 * NR + m0 + cq0 * 4];
    const float* srcX1 = &Xt[(size_t)ck1 * NR + m0 + cq1 * 4];
    const float* srcW0 = &Wt[(size_t)ck0 * HIDN + n0 + cq0 * 4];
    const float* srcW1 = &Wt[(size_t)ck1 * HIDN + n0 + cq1 * 4];

    // prologue: fill stage 0
    cp16(dstX0, srcX0);
    cp16(dstX1, srcX1);
    cp16(dstW0, srcW0);
    cp16(dstW1, srcW1);
    cp_commit();

    unsigned long long acc[2][4];
    #pragma unroll
    for (int p = 0; p < 2; p++)
        #pragma unroll
        for (int c = 0; c < 4; c++) acc[p][c] = 0ull;

    const int NT = DD / S1BK;  // 16 tiles
    for (int t = 0; t < NT; t++) {
        const int buf = t & 1;
        if (t + 1 < NT) {
            const unsigned off = (t + 1) & 1 ? bufStride : 0u;
            const size_t kxo = (size_t)(t + 1) * S1BK;
            cp16(dstX0 + off, srcX0 + kxo * NR);
            cp16(dstX1 + off, srcX1 + kxo * NR);
            cp16(dstW0 + off, srcW0 + kxo * HIDN);
            cp16(dstW1 + off, srcW1 + kxo * HIDN);
            cp_commit();
            cp_wait1();
        } else {
            cp_wait0();
        }
        __syncthreads();

        #pragma unroll
        for (int k = 0; k < S1BK; k++) {
            ulonglong2 a = *reinterpret_cast<const ulonglong2*>(&sX[buf][k][rg * 4]);
            float4 wv = *reinterpret_cast<const float4*>(&sW[buf][k][cg * 4]);
            unsigned long long w0 = dup2(wv.x);
            unsigned long long w1 = dup2(wv.y);
            unsigned long long w2 = dup2(wv.z);
            unsigned long long w3 = dup2(wv.w);
            acc[0][0] = ffma2(a.x, w0, acc[0][0]);
            acc[0][1] = ffma2(a.x, w1, acc[0][1]);
            acc[0][2] = ffma2(a.x, w2, acc[0][2]);
            acc[0][3] = ffma2(a.x, w3, acc[0][3]);
            acc[1][0] = ffma2(a.y, w0, acc[1][0]);
            acc[1][1] = ffma2(a.y, w1, acc[1][1]);
            acc[1][2] = ffma2(a.y, w2, acc[1][2]);
            acc[1][3] = ffma2(a.y, w3, acc[1][3]);
        }
        __syncthreads();
    }

    // Epilogue: acc[p][c] = rows (rg*4+2p, rg*4+2p+1), col cg*4+c
    float bias[4] = {0.f, 0.f, 0.f, 0.f};
    if (z == 0) {
        #pragma unroll
        for (int c = 0; c < 4; c++) bias[c] = b1[n0 + cg * 4 + c];
    }
    #pragma unroll
    for (int p = 0; p < 2; p++) {
        float2 c0 = unpk2(acc[p][0]);
        float2 c1 = unpk2(acc[p][1]);
        float2 c2 = unpk2(acc[p][2]);
        float2 c3 = unpk2(acc[p][3]);
        const int rlo = m0 + rg * 4 + 2 * p;
        float4 olo, ohi;
        olo.x = c0.x + bias[0]; olo.y = c1.x + bias[1];
        olo.z = c2.x + bias[2]; olo.w = c3.x + bias[3];
        ohi.x = c0.y + bias[0]; ohi.y = c1.y + bias[1];
        ohi.z = c2.y + bias[2]; ohi.w = c3.y + bias[3];
        *reinterpret_cast<float4*>(&C[(size_t)rlo * HIDN + n0 + cg * 4]) = olo;
        *reinterpret_cast<float4*>(&C[(size_t)(rlo + 1) * HIDN + n0 + cg * 4]) = ohi;
    }
}

// ---------------------------------------------------------------------------
// Kernel C: stage2. out[i,j,b,c] = sum_h relu(ha'[i,b,h]+hb[j,b,h])*W2[c,h]+b2[c]
// 256 threads, 32x16 (i,j) tile, grid (3, 6, 16) = 288 blocks (2 per SM).
// Dual accumulator chains (even/odd hq) for ILP; channel-packed f32x2.
// ---------------------------------------------------------------------------
#define TI 32
#define TJ 16
#define PADH 132

__global__ __launch_bounds__(256) void stage2_kernel(
    const float* __restrict__ W2, const float* __restrict__ b2,
    float* __restrict__ out)
{
    __shared__ float sA[TI][PADH];
    __shared__ float sB[TJ][PADH];
    __shared__ unsigned long long sW2p[HIDN];  // (W2[0][h], W2[1][h])

    const int i0  = blockIdx.x * TI;
    const int j0  = blockIdx.y * TJ;
    const int b   = blockIdx.z;
    const int tid = threadIdx.x;

    #pragma unroll
    for (int p = 0; p < 4; p++) {
        const int q   = tid + p * 256;  // 0..1023
        const int row = q >> 5;         // 0..31
        const int hq  = q & 31;
        float4 va = *reinterpret_cast<const float4*>(
            &g_ha[((size_t)(i0 + row) * BB + b) * HIDN + hq * 4]);
        *reinterpret_cast<float4*>(&sA[row][hq * 4]) = va;
    }
    #pragma unroll
    for (int p = 0; p < 2; p++) {
        const int q   = tid + p * 256;  // 0..511
        const int row = q >> 5;         // 0..15
        const int hq  = q & 31;
        float4 vb = *reinterpret_cast<const float4*>(
            &g_hb[((size_t)(j0 + row) * BB + b) * HIDN + hq * 4]);
        *reinterpret_cast<float4*>(&sB[row][hq * 4]) = vb;
    }
    if (tid < HIDN) {
        float w0 = W2[tid];
        float w1 = W2[HIDN + tid];
        unsigned long long pk;
        asm("mov.b64 %0, {%1, %2};" : "=l"(pk) : "f"(w0), "f"(w1));
        sW2p[tid] = pk;
    }
    __syncthreads();

    const int rg = tid >> 3;   // 0..31 -> i row
    const int cg = tid & 7;    // 0..7  -> j cols cg, cg+8

    unsigned long long accA[2] = {0ull, 0ull};  // (i, j=cg), even/odd chains
    unsigned long long accB[2] = {0ull, 0ull};  // (i, j=cg+8)

    #pragma unroll
    for (int hq = 0; hq < HIDN / 4; hq++) {
        float4 a  = *reinterpret_cast<const float4*>(&sA[rg][hq * 4]);
        float4 q0 = *reinterpret_cast<const float4*>(&sB[cg][hq * 4]);
        float4 q1 = *reinterpret_cast<const float4*>(&sB[cg + 8][hq * 4]);
        ulonglong2 wA = *reinterpret_cast<const ulonglong2*>(&sW2p[hq * 4]);
        ulonglong2 wB = *reinterpret_cast<const ulonglong2*>(&sW2p[hq * 4 + 2]);

        float av[4]  = {a.x, a.y, a.z, a.w};
        float q0v[4] = {q0.x, q0.y, q0.z, q0.w};
        float q1v[4] = {q1.x, q1.y, q1.z, q1.w};
        unsigned long long wv[4] = {wA.x, wA.y, wB.x, wB.y};

        #pragma unroll
        for (int l = 0; l < 4; l++) {
            const int ch = l & 1;  // split into two independent chains
            float v0 = fmaxf(av[l] + q0v[l], 0.0f);
            accA[ch] = ffma2(dup2(v0), wv[l], accA[ch]);
            float v1 = fmaxf(av[l] + q1v[l], 0.0f);
            accB[ch] = ffma2(dup2(v1), wv[l], accB[ch]);
        }
    }

    const float bb0 = b2[0];
    const float bb1 = b2[1];
    {
        float2 r0 = unpk2(accA[0]);
        float2 r1 = unpk2(accA[1]);
        const size_t idx = (((size_t)(i0 + rg) * SS + (j0 + cg)) * BB + b) * 2;
        float2 o; o.x = r0.x + r1.x + bb0; o.y = r0.y + r1.y + bb1;
        *reinterpret_cast<float2*>(&out[idx]) = o;
    }
    {
        float2 r0 = unpk2(accB[0]);
        float2 r1 = unpk2(accB[1]);
        const size_t idx = (((size_t)(i0 + rg) * SS + (j0 + cg + 8)) * BB + b) * 2;
        float2 o; o.x = r0.x + r1.x + bb0; o.y = r0.y + r1.y + bb1;
        *reinterpret_cast<float2*>(&out[idx]) = o;
    }
}

// ---------------------------------------------------------------------------
// Inputs: embeds, umask, qmask, embeds_cmp, W1, b1, W2, b2
// ---------------------------------------------------------------------------
extern "C" void kernel_launch(void* const* d_in, const int* in_sizes, int n_in,
                              void* d_out, int out_size)
{
    const float* embeds     = (const float*)d_in[0];
    const float* embeds_cmp = (const float*)d_in[3];
    const float* W1         = (const float*)d_in[4];
    const float* b1         = (const float*)d_in[5];
    const float* W2         = (const float*)d_in[6];
    const float* b2         = (const float*)d_in[7];
    float* out = (float*)d_out;

    prep_kernel<<<dim3(49, 16, 2), 256>>>(embeds, embeds_cmp, W1);
    stage1_kernel<<<dim3(24, 2, 2), 256>>>(b1);
    stage2_kernel<<<dim3(3, 6, 16), 256>>>(W2, b2, out);
}

// round 5
// speedup vs baseline: 1.3495x; 1.1452x over previous
#include <cuda_runtime.h>

// Problem constants
#define SS   96
#define BB   16
#define DD   512
#define HIDN 128
#define NR   (SS * BB)   // 1536 rows

// Scratch (__device__ globals: allocation-free rule)
__device__ float g_ha[NR * HIDN];      // ha + b1
__device__ float g_hb[NR * HIDN];

// ---------------------------------------------------------------------------
// f32x2 helpers
// ---------------------------------------------------------------------------
__device__ __forceinline__ unsigned long long ffma2(
    unsigned long long a, unsigned long long b, unsigned long long c)
{
    unsigned long long d;
    asm("fma.rn.f32x2 %0, %1, %2, %3;" : "=l"(d) : "l"(a), "l"(b), "l"(c));
    return d;
}
__device__ __forceinline__ unsigned long long dup2(float v)
{
    unsigned long long d;
    asm("mov.b64 %0, {%1, %1};" : "=l"(d) : "f"(v));
    return d;
}
__device__ __forceinline__ float2 unpk2(unsigned long long v)
{
    float2 f;
    asm("mov.b64 {%0, %1}, %2;" : "=f"(f.x), "=f"(f.y) : "l"(v));
    return f;
}

// cp.async 16B
__device__ __forceinline__ unsigned smem_u32(const void* p)
{
    unsigned a;
    asm("{ .reg .u64 t; cvta.to.shared.u64 t, %1; cvt.u32.u64 %0, t; }"
        : "=r"(a) : "l"(p));
    return a;
}
__device__ __forceinline__ void cp16(unsigned dst, const float* src)
{
    asm volatile("cp.async.cg.shared.global [%0], [%1], 16;" :: "r"(dst), "l"(src));
}
__device__ __forceinline__ void cp_commit() { asm volatile("cp.async.commit_group;"); }
__device__ __forceinline__ void cp_wait1()  { asm volatile("cp.async.wait_group 1;"); }
__device__ __forceinline__ void cp_wait0()  { asm volatile("cp.async.wait_group 0;"); }

// ---------------------------------------------------------------------------
// Stage 1 (dot-product form, f32x2 packed along k — NO transposes needed):
//   C[r][h] = sum_k X[r][k] * W[h][k]
// z=0: X=embeds,     W=W1 rows [:,0:512]    -> g_ha (+b1)
// z=1: X=embeds_cmp, W=W1 rows [:,512:1024] -> g_hb
// BM=48, BN=64, BK=32. 256 threads. Per thread: 3 rows (rg, rg+16, rg+32)
// x 4 cols (cg, cg+16, cg+32, cg+48). Accumulators are (even-k, odd-k) f32x2
// pairs; horizontal add in epilogue. Grid (32,2,2) = 128 blocks.
// ---------------------------------------------------------------------------
#define S1BK   32
#define S1LDW  36   // row stride in floats: 36/4=9 (odd) 16B-units -> conflict-free

__global__ __launch_bounds__(256) void stage1_kernel(
    const float* __restrict__ X0, const float* __restrict__ X1,
    const float* __restrict__ W1, const float* __restrict__ b1)
{
    __shared__ float sX[2][48][S1LDW];
    __shared__ float sW[2][64][S1LDW];

    const int mt = blockIdx.x;   // 0..31
    const int nt = blockIdx.y;   // 0..1
    const int z  = blockIdx.z;

    const float* __restrict__ X = z ? X1 : X0;
    const float* __restrict__ W = W1 + (size_t)z * DD;   // row stride 2*DD
    float* __restrict__ C = z ? g_hb : g_ha;

    const int tid = threadIdx.x;
    const int rg  = tid >> 4;    // 0..15
    const int cg  = tid & 15;    // 0..15
    const int m0  = mt * 48;
    const int n0  = nt * 64;

    // Fill mapping: X tile 48x32 = 384 float4; W tile 64x32 = 512 float4.
    const int xr0 = tid >> 3;          // 0..31  (row for X chunk 0)
    const int xk0 = tid & 7;           // float4 index along k
    const int xr1 = (tid + 256) >> 3;  // 32..63 (<48 only when tid<128)
    const int wr0 = tid >> 3;          // 0..31
    const int wr1 = (tid + 256) >> 3;  // 32..63

    unsigned dX0 = smem_u32(&sX[0][xr0][xk0 * 4]);
    unsigned dX1 = (tid < 128) ? smem_u32(&sX[0][xr1][xk0 * 4]) : 0u;
    unsigned dW0 = smem_u32(&sW[0][wr0][xk0 * 4]);
    unsigned dW1 = smem_u32(&sW[0][wr1][xk0 * 4]);
    const unsigned bufX = (unsigned)(48 * S1LDW * sizeof(float));
    const unsigned bufW = (unsigned)(64 * S1LDW * sizeof(float));

    const float* sXp0 = &X[(size_t)(m0 + xr0) * DD + xk0 * 4];
    const float* sXp1 = &X[(size_t)(m0 + xr1) * DD + xk0 * 4];
    const float* sWp0 = &W[(size_t)(n0 + wr0) * (2 * DD) + xk0 * 4];
    const float* sWp1 = &W[(size_t)(n0 + wr1) * (2 * DD) + xk0 * 4];

    // prologue: fill buffer 0 (k0 = 0)
    cp16(dX0, sXp0);
    if (tid < 128) cp16(dX1, sXp1);
    cp16(dW0, sWp0);
    cp16(dW1, sWp1);
    cp_commit();

    unsigned long long acc[3][4];
    #pragma unroll
    for (int r = 0; r < 3; r++)
        #pragma unroll
        for (int c = 0; c < 4; c++) acc[r][c] = 0ull;

    const int NT = DD / S1BK;  // 16
    for (int t = 0; t < NT; t++) {
        const int buf = t & 1;
        if (t + 1 < NT) {
            const unsigned offX = ((t + 1) & 1) ? bufX : 0u;
            const unsigned offW = ((t + 1) & 1) ? bufW : 0u;
            const int ko = (t + 1) * S1BK;
            cp16(dX0 + offX, sXp0 + ko);
            if (tid < 128) cp16(dX1 + offX, sXp1 + ko);
            cp16(dW0 + offW, sWp0 + ko);
            cp16(dW1 + offW, sWp1 + ko);
            cp_commit();
            cp_wait1();
        } else {
            cp_wait0();
        }
        __syncthreads();

        #pragma unroll
        for (int k4 = 0; k4 < S1BK / 4; k4++) {
            ulonglong2 a0 = *reinterpret_cast<const ulonglong2*>(&sX[buf][rg][k4 * 4]);
            ulonglong2 a1 = *reinterpret_cast<const ulonglong2*>(&sX[buf][rg + 16][k4 * 4]);
            ulonglong2 a2 = *reinterpret_cast<const ulonglong2*>(&sX[buf][rg + 32][k4 * 4]);
            ulonglong2 w0 = *reinterpret_cast<const ulonglong2*>(&sW[buf][cg][k4 * 4]);
            ulonglong2 w1 = *reinterpret_cast<const ulonglong2*>(&sW[buf][cg + 16][k4 * 4]);
            ulonglong2 w2 = *reinterpret_cast<const ulonglong2*>(&sW[buf][cg + 32][k4 * 4]);
            ulonglong2 w3 = *reinterpret_cast<const ulonglong2*>(&sW[buf][cg + 48][k4 * 4]);

            acc[0][0] = ffma2(a0.x, w0.x, acc[0][0]);
            acc[0][1] = ffma2(a0.x, w1.x, acc[0][1]);
            acc[0][2] = ffma2(a0.x, w2.x, acc[0][2]);
            acc[0][3] = ffma2(a0.x, w3.x, acc[0][3]);
            acc[1][0] = ffma2(a1.x, w0.x, acc[1][0]);
            acc[1][1] = ffma2(a1.x, w1.x, acc[1][1]);
            acc[1][2] = ffma2(a1.x, w2.x, acc[1][2]);
            acc[1][3] = ffma2(a1.x, w3.x, acc[1][3]);
            acc[2][0] = ffma2(a2.x, w0.x, acc[2][0]);
            acc[2][1] = ffma2(a2.x, w1.x, acc[2][1]);
            acc[2][2] = ffma2(a2.x, w2.x, acc[2][2]);
            acc[2][3] = ffma2(a2.x, w3.x, acc[2][3]);

            acc[0][0] = ffma2(a0.y, w0.y, acc[0][0]);
            acc[0][1] = ffma2(a0.y, w1.y, acc[0][1]);
            acc[0][2] = ffma2(a0.y, w2.y, acc[0][2]);
            acc[0][3] = ffma2(a0.y, w3.y, acc[0][3]);
            acc[1][0] = ffma2(a1.y, w0.y, acc[1][0]);
            acc[1][1] = ffma2(a1.y, w1.y, acc[1][1]);
            acc[1][2] = ffma2(a1.y, w2.y, acc[1][2]);
            acc[1][3] = ffma2(a1.y, w3.y, acc[1][3]);
            acc[2][0] = ffma2(a2.y, w0.y, acc[2][0]);
            acc[2][1] = ffma2(a2.y, w1.y, acc[2][1]);
            acc[2][2] = ffma2(a2.y, w2.y, acc[2][2]);
            acc[2][3] = ffma2(a2.y, w3.y, acc[2][3]);
        }
        __syncthreads();
    }

    // Epilogue: horizontal add of (even,odd) halves; + b1 for z=0.
    float bias[4] = {0.f, 0.f, 0.f, 0.f};
    if (z == 0) {
        #pragma unroll
        for (int c = 0; c < 4; c++) bias[c] = b1[n0 + cg + 16 * c];
    }
    #pragma unroll
    for (int r = 0; r < 3; r++) {
        const int row = m0 + rg + 16 * r;
        #pragma unroll
        for (int c = 0; c < 4; c++) {
            float2 p = unpk2(acc[r][c]);
            C[(size_t)row * HIDN + n0 + cg + 16 * c] = p.x + p.y + bias[c];
        }
    }
}

// ---------------------------------------------------------------------------
// Stage 2: out[i,j,b,c] = sum_h relu(ha'[i,b,h]+hb[j,b,h])*W2[c,h]+b2[c]
// 256 threads, 32x16 (i,j) tile, grid (3, 6, 16) = 288 blocks.
// Dual accumulator chains; channel-packed f32x2.
// ---------------------------------------------------------------------------
#define TI 32
#define TJ 16
#define PADH 132

__global__ __launch_bounds__(256) void stage2_kernel(
    const float* __restrict__ W2, const float* __restrict__ b2,
    float* __restrict__ out)
{
    __shared__ float sA[TI][PADH];
    __shared__ float sB[TJ][PADH];
    __shared__ unsigned long long sW2p[HIDN];  // (W2[0][h], W2[1][h])

    const int i0  = blockIdx.x * TI;
    const int j0  = blockIdx.y * TJ;
    const int b   = blockIdx.z;
    const int tid = threadIdx.x;

    #pragma unroll
    for (int p = 0; p < 4; p++) {
        const int q   = tid + p * 256;  // 0..1023
        const int row = q >> 5;         // 0..31
        const int hq  = q & 31;
        float4 va = *reinterpret_cast<const float4*>(
            &g_ha[((size_t)(i0 + row) * BB + b) * HIDN + hq * 4]);
        *reinterpret_cast<float4*>(&sA[row][hq * 4]) = va;
    }
    #pragma unroll
    for (int p = 0; p < 2; p++) {
        const int q   = tid + p * 256;  // 0..511
        const int row = q >> 5;         // 0..15
        const int hq  = q & 31;
        float4 vb = *reinterpret_cast<const float4*>(
            &g_hb[((size_t)(j0 + row) * BB + b) * HIDN + hq * 4]);
        *reinterpret_cast<float4*>(&sB[row][hq * 4]) = vb;
    }
    if (tid < HIDN) {
        float w0 = W2[tid];
        float w1 = W2[HIDN + tid];
        unsigned long long pk;
        asm("mov.b64 %0, {%1, %2};" : "=l"(pk) : "f"(w0), "f"(w1));
        sW2p[tid] = pk;
    }
    __syncthreads();

    const int rg = tid >> 3;   // 0..31 -> i row
    const int cg = tid & 7;    // 0..7  -> j cols cg, cg+8

    unsigned long long accA[2] = {0ull, 0ull};  // (i, j=cg)
    unsigned long long accB[2] = {0ull, 0ull};  // (i, j=cg+8)

    #pragma unroll
    for (int hq = 0; hq < HIDN / 4; hq++) {
        float4 a  = *reinterpret_cast<const float4*>(&sA[rg][hq * 4]);
        float4 q0 = *reinterpret_cast<const float4*>(&sB[cg][hq * 4]);
        float4 q1 = *reinterpret_cast<const float4*>(&sB[cg + 8][hq * 4]);
        ulonglong2 wA = *reinterpret_cast<const ulonglong2*>(&sW2p[hq * 4]);
        ulonglong2 wB = *reinterpret_cast<const ulonglong2*>(&sW2p[hq * 4 + 2]);

        float av[4]  = {a.x, a.y, a.z, a.w};
        float q0v[4] = {q0.x, q0.y, q0.z, q0.w};
        float q1v[4] = {q1.x, q1.y, q1.z, q1.w};
        unsigned long long wv[4] = {wA.x, wA.y, wB.x, wB.y};

        #pragma unroll
        for (int l = 0; l < 4; l++) {
            const int ch = l & 1;
            float v0 = fmaxf(av[l] + q0v[l], 0.0f);
            accA[ch] = ffma2(dup2(v0), wv[l], accA[ch]);
            float v1 = fmaxf(av[l] + q1v[l], 0.0f);
            accB[ch] = ffma2(dup2(v1), wv[l], accB[ch]);
        }
    }

    const float bb0 = b2[0];
    const float bb1 = b2[1];
    {
        float2 r0 = unpk2(accA[0]);
        float2 r1 = unpk2(accA[1]);
        const size_t idx = (((size_t)(i0 + rg) * SS + (j0 + cg)) * BB + b) * 2;
        float2 o; o.x = r0.x + r1.x + bb0; o.y = r0.y + r1.y + bb1;
        *reinterpret_cast<float2*>(&out[idx]) = o;
    }
    {
        float2 r0 = unpk2(accB[0]);
        float2 r1 = unpk2(accB[1]);
        const size_t idx = (((size_t)(i0 + rg) * SS + (j0 + cg + 8)) * BB + b) * 2;
        float2 o; o.x = r0.x + r1.x + bb0; o.y = r0.y + r1.y + bb1;
        *reinterpret_cast<float2*>(&out[idx]) = o;
    }
}

// ---------------------------------------------------------------------------
// Inputs: embeds, umask, qmask, embeds_cmp, W1, b1, W2, b2
// ---------------------------------------------------------------------------
extern "C" void kernel_launch(void* const* d_in, const int* in_sizes, int n_in,
                              void* d_out, int out_size)
{
    const float* embeds     = (const float*)d_in[0];
    const float* embeds_cmp = (const float*)d_in[3];
    const float* W1         = (const float*)d_in[4];
    const float* b1         = (const float*)d_in[5];
    const float* W2         = (const float*)d_in[6];
    const float* b2         = (const float*)d_in[7];
    float* out = (float*)d_out;

    stage1_kernel<<<dim3(32, 2, 2), 256>>>(embeds, embeds_cmp, W1, b1);
    stage2_kernel<<<dim3(3, 6, 16), 256>>>(W2, b2, out);
}

// round 7
// speedup vs baseline: 1.9340x; 1.4332x over previous
#include <cuda_runtime.h>
#include <cuda_bf16.h>
#include <cstdint>

// Problem constants
#define SS   96
#define BB   16
#define DD   512
#define HIDN 128
#define NR   (SS * BB)   // 1536 rows

// Intermediate activations
__device__ float g_ha[NR * HIDN];      // ha + b1
__device__ float g_hb[NR * HIDN];

// ---------------------------------------------------------------------------
// Helpers
// ---------------------------------------------------------------------------
__device__ __forceinline__ unsigned smem_u32(const void* p)
{
    unsigned a;
    asm("{ .reg .u64 t; cvta.to.shared.u64 t, %1; cvt.u32.u64 %0, t; }"
        : "=r"(a) : "l"(p));
    return a;
}

// SW128 swizzle (Swizzle<3,4,3>)
__device__ __forceinline__ unsigned sw128(unsigned byte_off)
{
    return byte_off ^ ((byte_off >> 3) & 0x70);
}

// Split a float4 into bf16 hi (round-nearest) and bf16 lo (residual).
__device__ __forceinline__ void cvt_split(float4 v, uint2& hw, uint2& lw)
{
    __nv_bfloat162 h01 = __float22bfloat162_rn(make_float2(v.x, v.y));
    __nv_bfloat162 h23 = __float22bfloat162_rn(make_float2(v.z, v.w));
    float2 hf01 = __bfloat1622float2(h01);
    float2 hf23 = __bfloat1622float2(h23);
    __nv_bfloat162 l01 = __float22bfloat162_rn(
        make_float2(v.x - hf01.x, v.y - hf01.y));
    __nv_bfloat162 l23 = __float22bfloat162_rn(
        make_float2(v.z - hf23.x, v.w - hf23.y));
    hw.x = *reinterpret_cast<unsigned*>(&h01);
    hw.y = *reinterpret_cast<unsigned*>(&h23);
    lw.x = *reinterpret_cast<unsigned*>(&l01);
    lw.y = *reinterpret_cast<unsigned*>(&l23);
}

__device__ __forceinline__ void ldsm_x4(
    uint32_t& r0, uint32_t& r1, uint32_t& r2, uint32_t& r3, unsigned addr)
{
    asm volatile("ldmatrix.sync.aligned.m8n8.x4.shared.b16 {%0,%1,%2,%3}, [%4];"
                 : "=r"(r0), "=r"(r1), "=r"(r2), "=r"(r3) : "r"(addr));
}

__device__ __forceinline__ void mma_bf16(
    float* d, uint32_t a0, uint32_t a1, uint32_t a2, uint32_t a3,
    uint32_t b0, uint32_t b1)
{
    asm volatile(
        "mma.sync.aligned.m16n8k16.row.col.f32.bf16.bf16.f32 "
        "{%0,%1,%2,%3}, {%4,%5,%6,%7}, {%8,%9}, {%0,%1,%2,%3};"
        : "+f"(d[0]), "+f"(d[1]), "+f"(d[2]), "+f"(d[3])
        : "r"(a0), "r"(a1), "r"(a2), "r"(a3), "r"(b0), "r"(b1));
}

// ---------------------------------------------------------------------------
// Stage 1: bf16-split GEMM on legacy tensor cores (mma.sync m16n8k16).
//   C[r][h] = sum_k X[r][k] * W[h][k]
//   x = hi + lo (bf16); D += Ahi*Bhi + Ahi*Blo + Alo*Bhi  (fp32 acc)
// Block tile M=64, N=64; 8 warps = 2(m) x 4(n); warp tile 32x16.
// K chunked by 64 (one SW128 atom row: 64 bf16 = 128B), double-buffered.
// Grid (24, 2, 2) = 96 blocks.
// ---------------------------------------------------------------------------
#define AHI_OFF   0
#define ALO_OFF   8192
#define BHI_OFF   16384
#define BLO_OFF   24576
#define BUF_BYTES 32768
#define S1_SMEM   (2 * BUF_BYTES)   // 65536

__global__ __launch_bounds__(256) void stage1_kernel(
    const float* __restrict__ X0, const float* __restrict__ X1,
    const float* __restrict__ W1, const float* __restrict__ b1)
{
    extern __shared__ char smem[];
    const unsigned sbase = smem_u32(smem);

    const int mt = blockIdx.x;   // 0..23
    const int nt = blockIdx.y;   // 0..1
    const int z  = blockIdx.z;   // 0..1
    const int m0 = mt * 64;
    const int n0 = nt * 64;

    const float* __restrict__ X = z ? X1 : X0;
    const float* __restrict__ W = W1 + (size_t)z * DD;   // row stride 2*DD
    float* __restrict__ C = z ? g_hb : g_ha;

    const int tid  = threadIdx.x;
    const int wid  = tid >> 5;
    const int lane = tid & 31;
    const int wm   = wid & 1;    // 0..1 -> m offset wm*32
    const int wn   = wid >> 1;   // 0..3 -> n offset wn*16

    // Fill coordinates: 4 float4 per thread per operand tile (64 rows x 16 q)
    int frow[4], fq[4];
    #pragma unroll
    for (int i = 0; i < 4; i++) {
        const int flat = tid + i * 256;
        frow[i] = flat >> 4;
        fq[i]   = flat & 15;
    }

    // ldmatrix lane addressing (byte offsets within a 64x128B tile)
    // A: row = wm*32 + mi*16 + lane%16, chunk16 = lane/16
    const int a_r   = (lane & 15);
    const int a_ch  = (lane >> 4);           // 0..1
    // B: n = wn*16 + (lane&7) + (lane>>4)*8, chunk16 = (lane>>3)&1
    const int b_n   = (lane & 7) + ((lane >> 4) << 3);
    const int b_ch  = (lane >> 3) & 1;

    float4 rA[4], rB[4];
    // prologue: load chunk 0
    #pragma unroll
    for (int i = 0; i < 4; i++) {
        rA[i] = *reinterpret_cast<const float4*>(
            &X[(size_t)(m0 + frow[i]) * DD + fq[i] * 4]);
        rB[i] = *reinterpret_cast<const float4*>(
            &W[(size_t)(n0 + frow[i]) * (2 * DD) + fq[i] * 4]);
    }

    float acc[2][2][4];
    #pragma unroll
    for (int mi = 0; mi < 2; mi++)
        #pragma unroll
        for (int ni = 0; ni < 2; ni++)
            #pragma unroll
            for (int r = 0; r < 4; r++) acc[mi][ni][r] = 0.0f;

    #pragma unroll 1
    for (int t = 0; t < 8; t++) {
        const unsigned bufOff = (unsigned)((t & 1) * BUF_BYTES);

        // ---- convert + store staged registers into smem (SW128) ----
        #pragma unroll
        for (int i = 0; i < 4; i++) {
            const unsigned so = sw128((unsigned)(frow[i] * 128 + fq[i] * 8));
            uint2 hw, lw;
            cvt_split(rA[i], hw, lw);
            *reinterpret_cast<uint2*>(smem + bufOff + AHI_OFF + so) = hw;
            *reinterpret_cast<uint2*>(smem + bufOff + ALO_OFF + so) = lw;
            cvt_split(rB[i], hw, lw);
            *reinterpret_cast<uint2*>(smem + bufOff + BHI_OFF + so) = hw;
            *reinterpret_cast<uint2*>(smem + bufOff + BLO_OFF + so) = lw;
        }
        __syncthreads();

        // ---- prefetch next chunk into registers ----
        if (t < 7) {
            const int k0 = (t + 1) * 64;
            #pragma unroll
            for (int i = 0; i < 4; i++) {
                rA[i] = *reinterpret_cast<const float4*>(
                    &X[(size_t)(m0 + frow[i]) * DD + k0 + fq[i] * 4]);
                rB[i] = *reinterpret_cast<const float4*>(
                    &W[(size_t)(n0 + frow[i]) * (2 * DD) + k0 + fq[i] * 4]);
            }
        }

        // ---- MMAs on this buffer: 4 k16 steps ----
        const unsigned aHi = sbase + bufOff + AHI_OFF;
        const unsigned aLo = sbase + bufOff + ALO_OFF;
        const unsigned bHi = sbase + bufOff + BHI_OFF;
        const unsigned bLo = sbase + bufOff + BLO_OFF;

        #pragma unroll
        for (int ks = 0; ks < 4; ks++) {
            const unsigned kb = (unsigned)(ks * 32);

            uint32_t ah[2][4], al[2][4];
            #pragma unroll
            for (int mi = 0; mi < 2; mi++) {
                const unsigned off = sw128(
                    (unsigned)((wm * 32 + mi * 16 + a_r) * 128) + kb + a_ch * 16);
                ldsm_x4(ah[mi][0], ah[mi][1], ah[mi][2], ah[mi][3], aHi + off);
                ldsm_x4(al[mi][0], al[mi][1], al[mi][2], al[mi][3], aLo + off);
            }
            uint32_t bh[4], bl[4];
            {
                const unsigned off = sw128(
                    (unsigned)((wn * 16 + b_n) * 128) + kb + b_ch * 16);
                ldsm_x4(bh[0], bh[1], bh[2], bh[3], bHi + off);
                ldsm_x4(bl[0], bl[1], bl[2], bl[3], bLo + off);
            }

            #pragma unroll
            for (int mi = 0; mi < 2; mi++) {
                #pragma unroll
                for (int ni = 0; ni < 2; ni++) {
                    mma_bf16(acc[mi][ni],
                             ah[mi][0], ah[mi][1], ah[mi][2], ah[mi][3],
                             bh[2 * ni], bh[2 * ni + 1]);
                    mma_bf16(acc[mi][ni],
                             ah[mi][0], ah[mi][1], ah[mi][2], ah[mi][3],
                             bl[2 * ni], bl[2 * ni + 1]);
                    mma_bf16(acc[mi][ni],
                             al[mi][0], al[mi][1], al[mi][2], al[mi][3],
                             bh[2 * ni], bh[2 * ni + 1]);
                }
            }
        }
        __syncthreads();
    }

    // ---- Epilogue: write D fragments (+ b1 for z=0) ----
    #pragma unroll
    for (int mi = 0; mi < 2; mi++) {
        #pragma unroll
        for (int ni = 0; ni < 2; ni++) {
            const int row = m0 + wm * 32 + mi * 16 + (lane >> 2);
            const int col = n0 + wn * 16 + ni * 8 + (lane & 3) * 2;
            float2 bias = make_float2(0.f, 0.f);
            if (z == 0)
                bias = *reinterpret_cast<const float2*>(&b1[col]);
            float2 o0, o1;
            o0.x = acc[mi][ni][0] + bias.x;
            o0.y = acc[mi][ni][1] + bias.y;
            o1.x = acc[mi][ni][2] + bias.x;
            o1.y = acc[mi][ni][3] + bias.y;
            *reinterpret_cast<float2*>(&C[(size_t)row * HIDN + col]) = o0;
            *reinterpret_cast<float2*>(&C[(size_t)(row + 8) * HIDN + col]) = o1;
        }
    }
}

// ---------------------------------------------------------------------------
// Stage 2 (round-1 best variant): 
//   out[i,j,b,c] = sum_h relu(ha'[i,b,h]+hb[j,b,h])*W2[c,h]+b2[c]
// Grid (3,3,16): 32x32 (i,j) tile per block at fixed b. 256 threads,
// each thread computes 2x2 pairs.
// ---------------------------------------------------------------------------
#define TI 32
#define TJ 32
#define PADH 132  // 128+4 -> reduced bank conflicts, 16B aligned

__global__ __launch_bounds__(256) void stage2_kernel(
    const float* __restrict__ W2, const float* __restrict__ b2,
    float* __restrict__ out)
{
    __shared__ float sA[TI][PADH];
    __shared__ float sB[TJ][PADH];
    __shared__ float sW2[2 * HIDN];

    const int i0  = blockIdx.x * TI;
    const int j0  = blockIdx.y * TJ;
    const int b   = blockIdx.z;
    const int tid = threadIdx.x;

    #pragma unroll
    for (int i = 0; i < 4; i++) {
        const int q   = tid + i * 256;  // 0..1023
        const int row = q >> 5;         // 0..31
        const int hq  = q & 31;         // float4 index along h

        float4 va = *reinterpret_cast<const float4*>(
            &g_ha[((size_t)(i0 + row) * BB + b) * HIDN + hq * 4]);
        *reinterpret_cast<float4*>(&sA[row][hq * 4]) = va;

        float4 vb = *reinterpret_cast<const float4*>(
            &g_hb[((size_t)(j0 + row) * BB + b) * HIDN + hq * 4]);
        *reinterpret_cast<float4*>(&sB[row][hq * 4]) = vb;
    }
    if (tid < 64) {
        float4 w = *reinterpret_cast<const float4*>(&W2[tid * 4]);
        *reinterpret_cast<float4*>(&sW2[tid * 4]) = w;
    }
    __syncthreads();

    const int rg = tid >> 4;   // 0..15
    const int cg = tid & 15;   // 0..15

    float acc[2][2][2];
    #pragma unroll
    for (int ii = 0; ii < 2; ii++)
        #pragma unroll
        for (int jj = 0; jj < 2; jj++) {
            acc[ii][jj][0] = 0.0f;
            acc[ii][jj][1] = 0.0f;
        }

    #pragma unroll
    for (int hq = 0; hq < HIDN / 4; hq++) {
        float4 a0 = *reinterpret_cast<const float4*>(&sA[rg][hq * 4]);
        float4 a1 = *reinterpret_cast<const float4*>(&sA[rg + 16][hq * 4]);
        float4 q0 = *reinterpret_cast<const float4*>(&sB[cg][hq * 4]);
        float4 q1 = *reinterpret_cast<const float4*>(&sB[cg + 16][hq * 4]);
        float4 w0 = *reinterpret_cast<const float4*>(&sW2[hq * 4]);
        float4 w1 = *reinterpret_cast<const float4*>(&sW2[HIDN + hq * 4]);

        float av[2][4] = {{a0.x, a0.y, a0.z, a0.w}, {a1.x, a1.y, a1.z, a1.w}};
        float qv[2][4] = {{q0.x, q0.y, q0.z, q0.w}, {q1.x, q1.y, q1.z, q1.w}};
        float w0v[4]   = {w0.x, w0.y, w0.z, w0.w};
        float w1v[4]   = {w1.x, w1.y, w1.z, w1.w};

        #pragma unroll
        for (int ii = 0; ii < 2; ii++)
            #pragma unroll
            for (int jj = 0; jj < 2; jj++)
                #pragma unroll
                for (int l = 0; l < 4; l++) {
                    float v = fmaxf(av[ii][l] + qv[jj][l], 0.0f);
                    acc[ii][jj][0] = fmaf(v, w0v[l], acc[ii][jj][0]);
                    acc[ii][jj][1] = fmaf(v, w1v[l], acc[ii][jj][1]);
                }
    }

    const float bb0 = b2[0];
    const float bb1 = b2[1];
    #pragma unroll
    for (int ii = 0; ii < 2; ii++)
        #pragma unroll
        for (int jj = 0; jj < 2; jj++) {
            const int i = i0 + rg + ii * 16;
            const int j = j0 + cg + jj * 16;
            const size_t idx = (((size_t)i * SS + j) * BB + b) * 2;
            float2 o;
            o.x = acc[ii][jj][0] + bb0;
            o.y = acc[ii][jj][1] + bb1;
            *reinterpret_cast<float2*>(&out[idx]) = o;
        }
}

// ---------------------------------------------------------------------------
// Inputs: embeds, umask, qmask, embeds_cmp, W1, b1, W2, b2
// ---------------------------------------------------------------------------
extern "C" void kernel_launch(void* const* d_in, const int* in_sizes, int n_in,
                              void* d_out, int out_size)
{
    const float* embeds     = (const float*)d_in[0];
    const float* embeds_cmp = (const float*)d_in[3];
    const float* W1         = (const float*)d_in[4];
    const float* b1         = (const float*)d_in[5];
    const float* W2         = (const float*)d_in[6];
    const float* b2         = (const float*)d_in[7];
    float* out = (float*)d_out;

    cudaFuncSetAttribute(stage1_kernel,
                         cudaFuncAttributeMaxDynamicSharedMemorySize, S1_SMEM);

    stage1_kernel<<<dim3(24, 2, 2), 256, S1_SMEM>>>(embeds, embeds_cmp, W1, b1);
    stage2_kernel<<<dim3(3, 3, 16), 256>>>(W2, b2, out);
}